// round 12
// baseline (speedup 1.0000x reference)
#include <cuda_runtime.h>
#include <cuda_fp16.h>
#include <cstdint>

#define B_DIM 512
#define D_IN  2048
#define D_H   8192
#define D_OUT 2048
#define SPLITK 4

#define N1E (D_H * D_IN)               // 16.8M
#define N2E (D_OUT * D_H)              // 16.8M
#define NXE (B_DIM * D_IN)             // 1.05M
#define W1B  (N1E / 4096)              // 4096 w1-dequant blocks
#define XB   (NXE / 4096)              // 256 x-convert blocks
#define G1B  256                       // gemm1 tiles
#define W2B  (N2E / 4096)              // 4096 w2-dequant blocks

// Scratch (static __device__ => allocation-rule safe)
__device__ __half g_x16[B_DIM * D_IN];
__device__ __half g_h[(size_t)B_DIM * D_H];
__device__ __half g_w1h[(size_t)D_H * D_IN];
__device__ __half g_w2h[(size_t)D_OUT * D_H];
__device__ int    g_tix[64];           // per-output-tile ticket (gemm2 ordered epilogue)

// ---------------- helpers ----------------
__device__ __forceinline__ uint32_t smem_u32(const void* p) {
    uint32_t a;
    asm("{ .reg .u64 t; cvta.to.shared.u64 t, %1; cvt.u32.u64 %0, t; }" : "=r"(a) : "l"(p));
    return a;
}
__device__ __forceinline__ void cp_async16(uint32_t dst, const void* src) {
    asm volatile("cp.async.cg.shared.global [%0], [%1], 16;" :: "r"(dst), "l"(src));
}
#define CP_COMMIT() asm volatile("cp.async.commit_group;" ::: "memory")
#define CP_WAIT1()  asm volatile("cp.async.wait_group 1;" ::: "memory")
#define CP_WAIT0()  asm volatile("cp.async.wait_group 0;" ::: "memory")

__device__ __forceinline__ void ldsm4(uint32_t& r0, uint32_t& r1, uint32_t& r2, uint32_t& r3,
                                      uint32_t addr) {
    asm volatile("ldmatrix.sync.aligned.m8n8.x4.shared.b16 {%0,%1,%2,%3}, [%4];"
                 : "=r"(r0), "=r"(r1), "=r"(r2), "=r"(r3) : "r"(addr));
}
__device__ __forceinline__ void mma16816(float* c, const uint32_t* a, const uint32_t* b) {
    asm volatile("mma.sync.aligned.m16n8k16.row.col.f32.f16.f16.f32 "
                 "{%0,%1,%2,%3}, {%4,%5,%6,%7}, {%8,%9}, {%0,%1,%2,%3};"
                 : "+f"(c[0]), "+f"(c[1]), "+f"(c[2]), "+f"(c[3])
                 : "r"(a[0]), "r"(a[1]), "r"(a[2]), "r"(a[3]), "r"(b[0]), "r"(b[1]));
}

// ---------------- dequant: 16 fp16 elems at offset e (never crosses a group) ----------------
template<int KSHIFT>
__device__ __forceinline__ void dequant16(const int* __restrict__ q, const float* __restrict__ S,
                                          const float* __restrict__ Z, __half* __restrict__ w,
                                          long long e)
{
    const int row = (int)(e >> KSHIFT);
    const int col = (int)(e & ((1 << KSHIFT) - 1));
    const int g   = col >> 7;
    constexpr int NG = 1 << (KSHIFT - 7);

    const int4* qp = (const int4*)(q + e);
    int4 qa = qp[0], qb = qp[1], qc = qp[2], qd = qp[3];
    const float s = __ldg(S + (size_t)row * NG + g);
    const float z = __ldg(Z + (size_t)row * NG + g);

    uint4 st0, st1;
    {
        __half2 h0 = __floats2half2_rn(((float)qa.x - z) * s, ((float)qa.y - z) * s);
        __half2 h1 = __floats2half2_rn(((float)qa.z - z) * s, ((float)qa.w - z) * s);
        __half2 h2 = __floats2half2_rn(((float)qb.x - z) * s, ((float)qb.y - z) * s);
        __half2 h3 = __floats2half2_rn(((float)qb.z - z) * s, ((float)qb.w - z) * s);
        st0.x = *(uint32_t*)&h0; st0.y = *(uint32_t*)&h1;
        st0.z = *(uint32_t*)&h2; st0.w = *(uint32_t*)&h3;
    }
    {
        __half2 h0 = __floats2half2_rn(((float)qc.x - z) * s, ((float)qc.y - z) * s);
        __half2 h1 = __floats2half2_rn(((float)qc.z - z) * s, ((float)qc.w - z) * s);
        __half2 h2 = __floats2half2_rn(((float)qd.x - z) * s, ((float)qd.y - z) * s);
        __half2 h3 = __floats2half2_rn(((float)qd.z - z) * s, ((float)qd.w - z) * s);
        st1.x = *(uint32_t*)&h0; st1.y = *(uint32_t*)&h1;
        st1.z = *(uint32_t*)&h2; st1.w = *(uint32_t*)&h3;
    }
    uint4* wp = (uint4*)(w + e);
    wp[0] = st0;
    wp[1] = st1;
}

// ---------------- GEMM body: 256 thr, 128x128x64 tile, 64x32 warp tile, 3-stage ----------------
// EPI 0: bias+ReLU -> fp16 (layer 1).  EPI 1: ordered split-K accumulate -> fp32 out (layer 2).
template<int EPI>
__device__ __forceinline__ void
gemm_body(char* smem, int m0, int n0, int kz0, int NT,
          const __half* __restrict__ A, const __half* __restrict__ B,
          const float* __restrict__ bias, float* __restrict__ outF,
          __half* __restrict__ outH, int N, int K, int tile, int zc)
{
    constexpr int BM = 128, BN = 128, ST = 3;
    constexpr int MI = 4, NI = 4;               // 64x32 per warp
    constexpr int BK = 64;

    const int tid = threadIdx.x, wid = tid >> 5, lane = tid & 31;
    const int wm = (wid >> 2) * 64, wn = (wid & 3) * 32;

    const uint32_t sA = smem_u32(smem);
    const uint32_t strA = BM * 128, strB = BN * 128;
    const uint32_t sB = sA + ST * strA;

    float acc[MI][NI][4];
    #pragma unroll
    for (int mi = 0; mi < MI; mi++)
        #pragma unroll
        for (int ni = 0; ni < NI; ni++)
            #pragma unroll
            for (int j = 0; j < 4; j++) acc[mi][ni][j] = 0.0f;

    auto prefetch = [&](int it, int st) {
        const int kt = kz0 + it * BK;
        #pragma unroll
        for (int i = 0; i < 4; i++) {
            int ch = tid + i * 256, row = ch >> 3, c = ch & 7;
            cp_async16(sA + st * strA + row * 128 + ((c ^ (row & 7)) << 4),
                       A + (size_t)(m0 + row) * K + kt + c * 8);
        }
        #pragma unroll
        for (int i = 0; i < 4; i++) {
            int ch = tid + i * 256, row = ch >> 3, c = ch & 7;
            cp_async16(sB + st * strB + row * 128 + ((c ^ (row & 7)) << 4),
                       B + (size_t)(n0 + row) * K + kt + c * 8);
        }
        CP_COMMIT();
    };

    auto compute = [&](int st) {
        const uint32_t baseA = sA + st * strA;
        const uint32_t baseB = sB + st * strB;
        const int arow = wm + (lane & 15);
        const int bg = lane >> 3, brin = lane & 7;
        #pragma unroll
        for (int ks = 0; ks < 4; ks++) {
            uint32_t a[MI][4], b[NI][2];
            const int ac = ks * 2 + (lane >> 4);
            #pragma unroll
            for (int mi = 0; mi < MI; mi++) {
                int r = arow + mi * 16;
                ldsm4(a[mi][0], a[mi][1], a[mi][2], a[mi][3],
                      baseA + r * 128 + ((ac ^ (r & 7)) << 4));
            }
            #pragma unroll
            for (int ni = 0; ni < NI; ni += 2) {
                int r = wn + ni * 8 + ((bg & 2) ? 8 : 0) + brin;
                int c = ks * 2 + (bg & 1);
                uint32_t b0, b1, b2, b3;
                ldsm4(b0, b1, b2, b3, baseB + r * 128 + ((c ^ (r & 7)) << 4));
                b[ni][0] = b0; b[ni][1] = b1; b[ni + 1][0] = b2; b[ni + 1][1] = b3;
            }
            #pragma unroll
            for (int mi = 0; mi < MI; mi++)
                #pragma unroll
                for (int ni = 0; ni < NI; ni++)
                    mma16816(acc[mi][ni], a[mi], b[ni]);
        }
    };

    prefetch(0, 0);
    prefetch(1, 1);

    for (int it = 0; it < NT; ++it) {
        if (it == NT - 1) CP_WAIT0();   // tail: last tile fully landed
        else              CP_WAIT1();
        __syncthreads();
        if (it + 2 < NT) prefetch(it + 2, (it + 2) % ST);
        compute(it % ST);
    }

    if (EPI == 1) {
        // ordered split-K: wait for our ticket (z order => deterministic sum)
        if (tid == 0) {
            volatile int* f = &g_tix[tile];
            while (*f != zc) { __nanosleep(100); }
        }
        __syncthreads();
        __threadfence();   // acquire: order out reads after ticket observation
    }

    #pragma unroll
    for (int mi = 0; mi < MI; mi++) {
        const int r0 = m0 + wm + mi * 16 + (lane >> 2);
        const int r1 = r0 + 8;
        #pragma unroll
        for (int ni = 0; ni < NI; ni++) {
            const int col = n0 + wn + ni * 8 + ((lane & 3) * 2);
            if (EPI == 0) {
                const float b0v = __ldg(bias + col), b1v = __ldg(bias + col + 1);
                __half2 p0 = __floats2half2_rn(fmaxf(acc[mi][ni][0] + b0v, 0.0f),
                                               fmaxf(acc[mi][ni][1] + b1v, 0.0f));
                __half2 p1 = __floats2half2_rn(fmaxf(acc[mi][ni][2] + b0v, 0.0f),
                                               fmaxf(acc[mi][ni][3] + b1v, 0.0f));
                *(__half2*)(outH + (size_t)r0 * N + col) = p0;
                *(__half2*)(outH + (size_t)r1 * N + col) = p1;
            } else {
                float2* o0 = (float2*)(outF + (size_t)r0 * N + col);
                float2* o1 = (float2*)(outF + (size_t)r1 * N + col);
                if (zc == 0) {
                    const float b0v = __ldg(bias + col), b1v = __ldg(bias + col + 1);
                    *o0 = make_float2(b0v + acc[mi][ni][0], b1v + acc[mi][ni][1]);
                    *o1 = make_float2(b0v + acc[mi][ni][2], b1v + acc[mi][ni][3]);
                } else {
                    float2 c0 = *o0, c1 = *o1;
                    c0.x += acc[mi][ni][0]; c0.y += acc[mi][ni][1];
                    c1.x += acc[mi][ni][2]; c1.y += acc[mi][ni][3];
                    *o0 = c0; *o1 = c1;
                }
            }
        }
    }

    if (EPI == 1) {
        __threadfence();   // release: our out stores visible before ticket bump
        __syncthreads();
        if (tid == 0) atomicExch(&g_tix[tile], zc + 1);
    }
}

// ---------------- K1: w1 dequant + x convert (full occupancy) + zero tickets ----------------
__global__ void __launch_bounds__(256)
prep1_kernel(const int* __restrict__ q1, const float* __restrict__ s1,
             const float* __restrict__ z1, const float* __restrict__ x,
             __half* __restrict__ w1, __half* __restrict__ x16)
{
    if (blockIdx.x == 0 && threadIdx.x < 64) g_tix[threadIdx.x] = 0;   // reset per launch

    if (blockIdx.x < W1B) {
        long long e = ((long long)blockIdx.x * 256 + threadIdx.x) * 16;
        dequant16<11>(q1, s1, z1, w1, e);
    } else {
        const int i = ((blockIdx.x - W1B) * 256 + threadIdx.x) * 16;
        float4 v0 = *(const float4*)(x + i);
        float4 v1 = *(const float4*)(x + i + 4);
        float4 v2 = *(const float4*)(x + i + 8);
        float4 v3 = *(const float4*)(x + i + 12);
        uint4 st0, st1;
        {
            __half2 h0 = __floats2half2_rn(v0.x, v0.y), h1 = __floats2half2_rn(v0.z, v0.w);
            __half2 h2 = __floats2half2_rn(v1.x, v1.y), h3 = __floats2half2_rn(v1.z, v1.w);
            st0.x = *(uint32_t*)&h0; st0.y = *(uint32_t*)&h1;
            st0.z = *(uint32_t*)&h2; st0.w = *(uint32_t*)&h3;
        }
        {
            __half2 h0 = __floats2half2_rn(v2.x, v2.y), h1 = __floats2half2_rn(v2.z, v2.w);
            __half2 h2 = __floats2half2_rn(v3.x, v3.y), h3 = __floats2half2_rn(v3.z, v3.w);
            st1.x = *(uint32_t*)&h0; st1.y = *(uint32_t*)&h1;
            st1.z = *(uint32_t*)&h2; st1.w = *(uint32_t*)&h3;
        }
        uint4* op = (uint4*)(x16 + i);
        op[0] = st0;
        op[1] = st1;
    }
}

// ---------------- K2 fat: gemm1 tiles + w2 dequant backfill (R8 schedule) ----------------
__global__ void __launch_bounds__(256)
fat_kernel(const __half* __restrict__ x16, const __half* __restrict__ w1,
           const float* __restrict__ b1, __half* __restrict__ h,
           const int* __restrict__ q2, const float* __restrict__ s2,
           const float* __restrict__ z2, __half* __restrict__ w2)
{
    extern __shared__ char smem[];
    if (blockIdx.x < G1B) {
        const int m0 = (blockIdx.x & 3) * 128;
        const int n0 = (blockIdx.x >> 2) * 128;
        gemm_body<0>(smem, m0, n0, 0, D_IN / 64, x16, w1, b1, nullptr, h, D_H, D_IN, 0, 0);
    } else {
        const int j = blockIdx.x - G1B;
        dequant16<13>(q2, s2, z2, w2, (long long)j * 4096 + threadIdx.x * 16);
    }
}

// ---------------- K3: gemm2 split-K=4 with ordered in-place accumulation ----------------
__global__ void __launch_bounds__(256)
gemm2_kernel(const __half* __restrict__ h, const __half* __restrict__ w2,
             const float* __restrict__ b2, float* __restrict__ out)
{
    extern __shared__ char smem[];
    const int m0 = blockIdx.y * 128, n0 = blockIdx.x * 128;
    const int zc = blockIdx.z;
    const int tile = blockIdx.y * 16 + blockIdx.x;
    gemm_body<1>(smem, m0, n0, zc * (D_H / SPLITK), (D_H / SPLITK) / 64,
                 h, w2, b2, out, nullptr, D_OUT, D_H, tile, zc);
}

extern "C" void kernel_launch(void* const* d_in, const int* in_sizes, int n_in,
                              void* d_out, int out_size)
{
    const float* x  = (const float*)d_in[0];
    const int*   q1 = (const int*)  d_in[1];
    const float* s1 = (const float*)d_in[2];
    const float* z1 = (const float*)d_in[3];
    const float* b1 = (const float*)d_in[4];
    const int*   q2 = (const int*)  d_in[5];
    const float* s2 = (const float*)d_in[6];
    const float* z2 = (const float*)d_in[7];
    const float* b2 = (const float*)d_in[8];
    float* out = (float*)d_out;

    __half *x16, *h, *w1h, *w2h;
    cudaGetSymbolAddress((void**)&x16, g_x16);
    cudaGetSymbolAddress((void**)&h,   g_h);
    cudaGetSymbolAddress((void**)&w1h, g_w1h);
    cudaGetSymbolAddress((void**)&w2h, g_w2h);

    constexpr int SMEM = 3 * 128 * 128 * 2;   // 96 KB
    cudaFuncSetAttribute(fat_kernel,   cudaFuncAttributeMaxDynamicSharedMemorySize, SMEM);
    cudaFuncSetAttribute(gemm2_kernel, cudaFuncAttributeMaxDynamicSharedMemorySize, SMEM);

    // K1: w1 dequant + x convert (+ ticket reset)
    prep1_kernel<<<W1B + XB, 256>>>(q1, s1, z1, x, w1h, x16);

    // K2: gemm1 || w2 dequant backfill (R8 schedule)
    fat_kernel<<<G1B + W2B, 256, SMEM>>>(x16, w1h, b1, h, q2, s2, z2, w2h);

    // K3: gemm2 split-K=4, ordered accumulation straight into out (no reduce pass)
    dim3 g2(D_OUT / 128, B_DIM / 128, SPLITK);
    gemm2_kernel<<<g2, 256, SMEM>>>(h, w2h, b2, out);
}

// round 13
// speedup vs baseline: 1.3750x; 1.3750x over previous
#include <cuda_runtime.h>
#include <cuda_fp16.h>
#include <cstdint>

#define B_DIM 512
#define D_IN  2048
#define D_H   8192
#define D_OUT 2048
#define SPLITK 4

#define N1E (D_H * D_IN)               // 16.8M
#define N2E (D_OUT * D_H)              // 16.8M
#define NXE (B_DIM * D_IN)             // 1.05M
#define W1B  (N1E / 4096)              // 4096 w1-dequant blocks
#define XB   (NXE / 4096)              // 256 x-convert blocks
#define G1B  256                       // gemm1 tiles
#define W2B  (N2E / 4096)              // 4096 w2-dequant blocks

// Scratch (static __device__ => allocation-rule safe)
__device__ __half g_x16[B_DIM * D_IN];
__device__ __half g_h[(size_t)B_DIM * D_H];
__device__ __half g_w1h[(size_t)D_H * D_IN];
__device__ __half g_w2h[(size_t)D_OUT * D_H];
__device__ float  g_part[(size_t)SPLITK * B_DIM * D_OUT];
__device__ int    g_cnt[64];           // per-output-tile arrival counter (gemm2)

// ---------------- helpers ----------------
__device__ __forceinline__ uint32_t smem_u32(const void* p) {
    uint32_t a;
    asm("{ .reg .u64 t; cvta.to.shared.u64 t, %1; cvt.u32.u64 %0, t; }" : "=r"(a) : "l"(p));
    return a;
}
__device__ __forceinline__ void cp_async16(uint32_t dst, const void* src) {
    asm volatile("cp.async.cg.shared.global [%0], [%1], 16;" :: "r"(dst), "l"(src));
}
#define CP_COMMIT() asm volatile("cp.async.commit_group;" ::: "memory")
#define CP_WAIT1()  asm volatile("cp.async.wait_group 1;" ::: "memory")
#define CP_WAIT0()  asm volatile("cp.async.wait_group 0;" ::: "memory")

__device__ __forceinline__ void ldsm4(uint32_t& r0, uint32_t& r1, uint32_t& r2, uint32_t& r3,
                                      uint32_t addr) {
    asm volatile("ldmatrix.sync.aligned.m8n8.x4.shared.b16 {%0,%1,%2,%3}, [%4];"
                 : "=r"(r0), "=r"(r1), "=r"(r2), "=r"(r3) : "r"(addr));
}
__device__ __forceinline__ void mma16816(float* c, const uint32_t* a, const uint32_t* b) {
    asm volatile("mma.sync.aligned.m16n8k16.row.col.f32.f16.f16.f32 "
                 "{%0,%1,%2,%3}, {%4,%5,%6,%7}, {%8,%9}, {%0,%1,%2,%3};"
                 : "+f"(c[0]), "+f"(c[1]), "+f"(c[2]), "+f"(c[3])
                 : "r"(a[0]), "r"(a[1]), "r"(a[2]), "r"(a[3]), "r"(b[0]), "r"(b[1]));
}

// ---------------- dequant: 16 fp16 elems at offset e (never crosses a group) ----------------
template<int KSHIFT>
__device__ __forceinline__ void dequant16(const int* __restrict__ q, const float* __restrict__ S,
                                          const float* __restrict__ Z, __half* __restrict__ w,
                                          long long e)
{
    const int row = (int)(e >> KSHIFT);
    const int col = (int)(e & ((1 << KSHIFT) - 1));
    const int g   = col >> 7;
    constexpr int NG = 1 << (KSHIFT - 7);

    const int4* qp = (const int4*)(q + e);
    int4 qa = qp[0], qb = qp[1], qc = qp[2], qd = qp[3];
    const float s = __ldg(S + (size_t)row * NG + g);
    const float z = __ldg(Z + (size_t)row * NG + g);

    uint4 st0, st1;
    {
        __half2 h0 = __floats2half2_rn(((float)qa.x - z) * s, ((float)qa.y - z) * s);
        __half2 h1 = __floats2half2_rn(((float)qa.z - z) * s, ((float)qa.w - z) * s);
        __half2 h2 = __floats2half2_rn(((float)qb.x - z) * s, ((float)qb.y - z) * s);
        __half2 h3 = __floats2half2_rn(((float)qb.z - z) * s, ((float)qb.w - z) * s);
        st0.x = *(uint32_t*)&h0; st0.y = *(uint32_t*)&h1;
        st0.z = *(uint32_t*)&h2; st0.w = *(uint32_t*)&h3;
    }
    {
        __half2 h0 = __floats2half2_rn(((float)qc.x - z) * s, ((float)qc.y - z) * s);
        __half2 h1 = __floats2half2_rn(((float)qc.z - z) * s, ((float)qc.w - z) * s);
        __half2 h2 = __floats2half2_rn(((float)qd.x - z) * s, ((float)qd.y - z) * s);
        __half2 h3 = __floats2half2_rn(((float)qd.z - z) * s, ((float)qd.w - z) * s);
        st1.x = *(uint32_t*)&h0; st1.y = *(uint32_t*)&h1;
        st1.z = *(uint32_t*)&h2; st1.w = *(uint32_t*)&h3;
    }
    uint4* wp = (uint4*)(w + e);
    wp[0] = st0;
    wp[1] = st1;
}

// ---------------- GEMM body: 256 thr, 128x128x64 tile, 64x32 warp tile, 3-stage ----------------
// EPI 0: bias+ReLU -> fp16 (layer 1).
// EPI 1: write fp32 partial; last-arriving CTA of the tile reduces 4 partials + bias -> out.
template<int EPI>
__device__ __forceinline__ void
gemm_body(char* smem, int m0, int n0, int kz0, int NT,
          const __half* __restrict__ A, const __half* __restrict__ B,
          const float* __restrict__ bias, float* __restrict__ part,
          float* __restrict__ outF, __half* __restrict__ outH,
          int N, int K, int tile, int zc)
{
    constexpr int BM = 128, BN = 128, ST = 3;
    constexpr int MI = 4, NI = 4;               // 64x32 per warp
    constexpr int BK = 64;

    const int tid = threadIdx.x, wid = tid >> 5, lane = tid & 31;
    const int wm = (wid >> 2) * 64, wn = (wid & 3) * 32;

    const uint32_t sA = smem_u32(smem);
    const uint32_t strA = BM * 128, strB = BN * 128;
    const uint32_t sB = sA + ST * strA;

    float acc[MI][NI][4];
    #pragma unroll
    for (int mi = 0; mi < MI; mi++)
        #pragma unroll
        for (int ni = 0; ni < NI; ni++)
            #pragma unroll
            for (int j = 0; j < 4; j++) acc[mi][ni][j] = 0.0f;

    auto prefetch = [&](int it, int st) {
        const int kt = kz0 + it * BK;
        #pragma unroll
        for (int i = 0; i < 4; i++) {
            int ch = tid + i * 256, row = ch >> 3, c = ch & 7;
            cp_async16(sA + st * strA + row * 128 + ((c ^ (row & 7)) << 4),
                       A + (size_t)(m0 + row) * K + kt + c * 8);
        }
        #pragma unroll
        for (int i = 0; i < 4; i++) {
            int ch = tid + i * 256, row = ch >> 3, c = ch & 7;
            cp_async16(sB + st * strB + row * 128 + ((c ^ (row & 7)) << 4),
                       B + (size_t)(n0 + row) * K + kt + c * 8);
        }
        CP_COMMIT();
    };

    auto compute = [&](int st) {
        const uint32_t baseA = sA + st * strA;
        const uint32_t baseB = sB + st * strB;
        const int arow = wm + (lane & 15);
        const int bg = lane >> 3, brin = lane & 7;
        #pragma unroll
        for (int ks = 0; ks < 4; ks++) {
            uint32_t a[MI][4], b[NI][2];
            const int ac = ks * 2 + (lane >> 4);
            #pragma unroll
            for (int mi = 0; mi < MI; mi++) {
                int r = arow + mi * 16;
                ldsm4(a[mi][0], a[mi][1], a[mi][2], a[mi][3],
                      baseA + r * 128 + ((ac ^ (r & 7)) << 4));
            }
            #pragma unroll
            for (int ni = 0; ni < NI; ni += 2) {
                int r = wn + ni * 8 + ((bg & 2) ? 8 : 0) + brin;
                int c = ks * 2 + (bg & 1);
                uint32_t b0, b1, b2, b3;
                ldsm4(b0, b1, b2, b3, baseB + r * 128 + ((c ^ (r & 7)) << 4));
                b[ni][0] = b0; b[ni][1] = b1; b[ni + 1][0] = b2; b[ni + 1][1] = b3;
            }
            #pragma unroll
            for (int mi = 0; mi < MI; mi++)
                #pragma unroll
                for (int ni = 0; ni < NI; ni++)
                    mma16816(acc[mi][ni], a[mi], b[ni]);
        }
    };

    prefetch(0, 0);
    prefetch(1, 1);

    for (int it = 0; it < NT; ++it) {
        if (it == NT - 1) CP_WAIT0();   // tail: last tile fully landed
        else              CP_WAIT1();
        __syncthreads();
        if (it + 2 < NT) prefetch(it + 2, (it + 2) % ST);
        compute(it % ST);
    }

    // ---- epilogue ----
    #pragma unroll
    for (int mi = 0; mi < MI; mi++) {
        const int r0 = m0 + wm + mi * 16 + (lane >> 2);
        const int r1 = r0 + 8;
        #pragma unroll
        for (int ni = 0; ni < NI; ni++) {
            const int col = n0 + wn + ni * 8 + ((lane & 3) * 2);
            if (EPI == 0) {
                const float b0v = __ldg(bias + col), b1v = __ldg(bias + col + 1);
                __half2 p0 = __floats2half2_rn(fmaxf(acc[mi][ni][0] + b0v, 0.0f),
                                               fmaxf(acc[mi][ni][1] + b1v, 0.0f));
                __half2 p1 = __floats2half2_rn(fmaxf(acc[mi][ni][2] + b0v, 0.0f),
                                               fmaxf(acc[mi][ni][3] + b1v, 0.0f));
                *(__half2*)(outH + (size_t)r0 * N + col) = p0;
                *(__half2*)(outH + (size_t)r1 * N + col) = p1;
            } else {
                float* o = part + (size_t)zc * B_DIM * D_OUT;
                *(float2*)(o + (size_t)r0 * N + col) = make_float2(acc[mi][ni][0], acc[mi][ni][1]);
                *(float2*)(o + (size_t)r1 * N + col) = make_float2(acc[mi][ni][2], acc[mi][ni][3]);
            }
        }
    }

    if (EPI == 1) {
        // last-arrival reduction: no waiting, no ordering chain
        __threadfence();                  // release: partial stores visible
        __syncthreads();
        int* flag = (int*)smem;           // smem free after compute
        if (tid == 0)
            *flag = (atomicAdd(&g_cnt[tile], 1) == SPLITK - 1) ? 1 : 0;
        __syncthreads();
        if (*flag) {
            __threadfence();              // acquire: other CTAs' partials visible
            #pragma unroll
            for (int mi = 0; mi < MI; mi++) {
                const int r0 = m0 + wm + mi * 16 + (lane >> 2);
                const int r1 = r0 + 8;
                #pragma unroll
                for (int ni = 0; ni < NI; ni++) {
                    const int col = n0 + wn + ni * 8 + ((lane & 3) * 2);
                    const float b0v = __ldg(bias + col), b1v = __ldg(bias + col + 1);
                    float2 a0 = make_float2(b0v, b1v), a1 = make_float2(b0v, b1v);
                    #pragma unroll
                    for (int k = 0; k < SPLITK; k++) {   // fixed z order => deterministic
                        const float* p = part + (size_t)k * B_DIM * D_OUT;
                        float2 p0 = *(const float2*)(p + (size_t)r0 * N + col);
                        float2 p1 = *(const float2*)(p + (size_t)r1 * N + col);
                        a0.x += p0.x; a0.y += p0.y;
                        a1.x += p1.x; a1.y += p1.y;
                    }
                    *(float2*)(outF + (size_t)r0 * N + col) = a0;
                    *(float2*)(outF + (size_t)r1 * N + col) = a1;
                }
            }
        }
    }
}

// ---------------- K1: w1 dequant + x convert (full occupancy) + counter reset ----------------
__global__ void __launch_bounds__(256)
prep1_kernel(const int* __restrict__ q1, const float* __restrict__ s1,
             const float* __restrict__ z1, const float* __restrict__ x,
             __half* __restrict__ w1, __half* __restrict__ x16)
{
    if (blockIdx.x == 0 && threadIdx.x < 64) g_cnt[threadIdx.x] = 0;   // reset per launch

    if (blockIdx.x < W1B) {
        long long e = ((long long)blockIdx.x * 256 + threadIdx.x) * 16;
        dequant16<11>(q1, s1, z1, w1, e);
    } else {
        const int i = ((blockIdx.x - W1B) * 256 + threadIdx.x) * 16;
        float4 v0 = *(const float4*)(x + i);
        float4 v1 = *(const float4*)(x + i + 4);
        float4 v2 = *(const float4*)(x + i + 8);
        float4 v3 = *(const float4*)(x + i + 12);
        uint4 st0, st1;
        {
            __half2 h0 = __floats2half2_rn(v0.x, v0.y), h1 = __floats2half2_rn(v0.z, v0.w);
            __half2 h2 = __floats2half2_rn(v1.x, v1.y), h3 = __floats2half2_rn(v1.z, v1.w);
            st0.x = *(uint32_t*)&h0; st0.y = *(uint32_t*)&h1;
            st0.z = *(uint32_t*)&h2; st0.w = *(uint32_t*)&h3;
        }
        {
            __half2 h0 = __floats2half2_rn(v2.x, v2.y), h1 = __floats2half2_rn(v2.z, v2.w);
            __half2 h2 = __floats2half2_rn(v3.x, v3.y), h3 = __floats2half2_rn(v3.z, v3.w);
            st1.x = *(uint32_t*)&h0; st1.y = *(uint32_t*)&h1;
            st1.z = *(uint32_t*)&h2; st1.w = *(uint32_t*)&h3;
        }
        uint4* op = (uint4*)(x16 + i);
        op[0] = st0;
        op[1] = st1;
    }
}

// ---------------- K2 fat: gemm1 tiles + w2 dequant backfill (R8 schedule) ----------------
__global__ void __launch_bounds__(256)
fat_kernel(const __half* __restrict__ x16, const __half* __restrict__ w1,
           const float* __restrict__ b1, __half* __restrict__ h,
           const int* __restrict__ q2, const float* __restrict__ s2,
           const float* __restrict__ z2, __half* __restrict__ w2)
{
    extern __shared__ char smem[];
    if (blockIdx.x < G1B) {
        const int m0 = (blockIdx.x & 3) * 128;
        const int n0 = (blockIdx.x >> 2) * 128;
        gemm_body<0>(smem, m0, n0, 0, D_IN / 64, x16, w1, b1, nullptr, nullptr, h,
                     D_H, D_IN, 0, 0);
    } else {
        const int j = blockIdx.x - G1B;
        dequant16<13>(q2, s2, z2, w2, (long long)j * 4096 + threadIdx.x * 16);
    }
}

// ---------------- K3: gemm2 split-K=4, last-arrival reduction into out ----------------
__global__ void __launch_bounds__(256)
gemm2_kernel(const __half* __restrict__ h, const __half* __restrict__ w2,
             const float* __restrict__ b2, float* __restrict__ part,
             float* __restrict__ out)
{
    extern __shared__ char smem[];
    const int m0 = blockIdx.y * 128, n0 = blockIdx.x * 128;
    const int zc = blockIdx.z;
    const int tile = blockIdx.y * 16 + blockIdx.x;
    gemm_body<1>(smem, m0, n0, zc * (D_H / SPLITK), (D_H / SPLITK) / 64,
                 h, w2, b2, part, out, nullptr, D_OUT, D_H, tile, zc);
}

extern "C" void kernel_launch(void* const* d_in, const int* in_sizes, int n_in,
                              void* d_out, int out_size)
{
    const float* x  = (const float*)d_in[0];
    const int*   q1 = (const int*)  d_in[1];
    const float* s1 = (const float*)d_in[2];
    const float* z1 = (const float*)d_in[3];
    const float* b1 = (const float*)d_in[4];
    const int*   q2 = (const int*)  d_in[5];
    const float* s2 = (const float*)d_in[6];
    const float* z2 = (const float*)d_in[7];
    const float* b2 = (const float*)d_in[8];
    float* out = (float*)d_out;

    __half *x16, *h, *w1h, *w2h; float* part;
    cudaGetSymbolAddress((void**)&x16, g_x16);
    cudaGetSymbolAddress((void**)&h,   g_h);
    cudaGetSymbolAddress((void**)&w1h, g_w1h);
    cudaGetSymbolAddress((void**)&w2h, g_w2h);
    cudaGetSymbolAddress((void**)&part, g_part);

    constexpr int SMEM = 3 * 128 * 128 * 2;   // 96 KB
    cudaFuncSetAttribute(fat_kernel,   cudaFuncAttributeMaxDynamicSharedMemorySize, SMEM);
    cudaFuncSetAttribute(gemm2_kernel, cudaFuncAttributeMaxDynamicSharedMemorySize, SMEM);

    // K1: w1 dequant + x convert (+ counter reset)
    prep1_kernel<<<W1B + XB, 256>>>(q1, s1, z1, x, w1h, x16);

    // K2: gemm1 || w2 dequant backfill (R8 schedule)
    fat_kernel<<<G1B + W2B, 256, SMEM>>>(x16, w1h, b1, h, q2, s2, z2, w2h);

    // K3: gemm2 split-K=4 with fused last-arrival reduction (no reduce kernel)
    dim3 g2(D_OUT / 128, B_DIM / 128, SPLITK);
    gemm2_kernel<<<g2, 256, SMEM>>>(h, w2h, b2, part, out);
}

// round 14
// speedup vs baseline: 1.5242x; 1.1085x over previous
#include <cuda_runtime.h>
#include <cuda_fp16.h>
#include <cstdint>

#define B_DIM 512
#define D_IN  2048
#define D_H   8192
#define D_OUT 2048
#define SPLITK 4

#define N1E (D_H * D_IN)               // 16.8M
#define N2E (D_OUT * D_H)              // 16.8M
#define NXE (B_DIM * D_IN)             // 1.05M
#define W1B  (N1E / 4096)              // 4096 w1-dequant blocks
#define XB   (NXE / 4096)              // 256 x-convert blocks
#define G1B  256                       // gemm1 tiles
#define W2B  (N2E / 4096)              // 4096 w2-dequant blocks

// Scratch (static __device__ => allocation-rule safe)
__device__ __half g_x16[B_DIM * D_IN];
__device__ __half g_h[(size_t)B_DIM * D_H];
__device__ __half g_w1h[(size_t)D_H * D_IN];
__device__ __half g_w2h[(size_t)D_OUT * D_H];
__device__ float  g_part[(size_t)SPLITK * B_DIM * D_OUT];

// ---------------- helpers ----------------
__device__ __forceinline__ uint32_t smem_u32(const void* p) {
    uint32_t a;
    asm("{ .reg .u64 t; cvta.to.shared.u64 t, %1; cvt.u32.u64 %0, t; }" : "=r"(a) : "l"(p));
    return a;
}
__device__ __forceinline__ void cp_async16(uint32_t dst, const void* src) {
    asm volatile("cp.async.cg.shared.global [%0], [%1], 16;" :: "r"(dst), "l"(src));
}
#define CP_COMMIT() asm volatile("cp.async.commit_group;" ::: "memory")
#define CP_WAIT1()  asm volatile("cp.async.wait_group 1;" ::: "memory")
#define CP_WAIT0()  asm volatile("cp.async.wait_group 0;" ::: "memory")

__device__ __forceinline__ void ldsm4(uint32_t& r0, uint32_t& r1, uint32_t& r2, uint32_t& r3,
                                      uint32_t addr) {
    asm volatile("ldmatrix.sync.aligned.m8n8.x4.shared.b16 {%0,%1,%2,%3}, [%4];"
                 : "=r"(r0), "=r"(r1), "=r"(r2), "=r"(r3) : "r"(addr));
}
__device__ __forceinline__ void mma16816(float* c, const uint32_t* a, const uint32_t* b) {
    asm volatile("mma.sync.aligned.m16n8k16.row.col.f32.f16.f16.f32 "
                 "{%0,%1,%2,%3}, {%4,%5,%6,%7}, {%8,%9}, {%0,%1,%2,%3};"
                 : "+f"(c[0]), "+f"(c[1]), "+f"(c[2]), "+f"(c[3])
                 : "r"(a[0]), "r"(a[1]), "r"(a[2]), "r"(a[3]), "r"(b[0]), "r"(b[1]));
}

// ---------------- dequant: 16 fp16 elems at offset e (never crosses a group) ----------------
template<int KSHIFT>
__device__ __forceinline__ void dequant16(const int* __restrict__ q, const float* __restrict__ S,
                                          const float* __restrict__ Z, __half* __restrict__ w,
                                          long long e)
{
    const int row = (int)(e >> KSHIFT);
    const int col = (int)(e & ((1 << KSHIFT) - 1));
    const int g   = col >> 7;
    constexpr int NG = 1 << (KSHIFT - 7);

    const int4* qp = (const int4*)(q + e);
    int4 qa = qp[0], qb = qp[1], qc = qp[2], qd = qp[3];
    const float s = __ldg(S + (size_t)row * NG + g);
    const float z = __ldg(Z + (size_t)row * NG + g);

    uint4 st0, st1;
    {
        __half2 h0 = __floats2half2_rn(((float)qa.x - z) * s, ((float)qa.y - z) * s);
        __half2 h1 = __floats2half2_rn(((float)qa.z - z) * s, ((float)qa.w - z) * s);
        __half2 h2 = __floats2half2_rn(((float)qb.x - z) * s, ((float)qb.y - z) * s);
        __half2 h3 = __floats2half2_rn(((float)qb.z - z) * s, ((float)qb.w - z) * s);
        st0.x = *(uint32_t*)&h0; st0.y = *(uint32_t*)&h1;
        st0.z = *(uint32_t*)&h2; st0.w = *(uint32_t*)&h3;
    }
    {
        __half2 h0 = __floats2half2_rn(((float)qc.x - z) * s, ((float)qc.y - z) * s);
        __half2 h1 = __floats2half2_rn(((float)qc.z - z) * s, ((float)qc.w - z) * s);
        __half2 h2 = __floats2half2_rn(((float)qd.x - z) * s, ((float)qd.y - z) * s);
        __half2 h3 = __floats2half2_rn(((float)qd.z - z) * s, ((float)qd.w - z) * s);
        st1.x = *(uint32_t*)&h0; st1.y = *(uint32_t*)&h1;
        st1.z = *(uint32_t*)&h2; st1.w = *(uint32_t*)&h3;
    }
    uint4* wp = (uint4*)(w + e);
    wp[0] = st0;
    wp[1] = st1;
}

// ---------------- GEMM body: 256 thr, 128x128x64 tile, 64x32 warp tile, 3-stage ----------------
template<bool IS_L1>
__device__ __forceinline__ void
gemm_body(char* smem, int m0, int n0, int kz0, int NT,
          const __half* __restrict__ A, const __half* __restrict__ B,
          const float* __restrict__ bias, float* __restrict__ outF,
          __half* __restrict__ outH, int N, int K)
{
    constexpr int BM = 128, BN = 128, ST = 3;
    constexpr int MI = 4, NI = 4;               // 64x32 per warp
    constexpr int BK = 64;

    const int tid = threadIdx.x, wid = tid >> 5, lane = tid & 31;
    const int wm = (wid >> 2) * 64, wn = (wid & 3) * 32;

    const uint32_t sA = smem_u32(smem);
    const uint32_t strA = BM * 128, strB = BN * 128;
    const uint32_t sB = sA + ST * strA;

    float acc[MI][NI][4];
    #pragma unroll
    for (int mi = 0; mi < MI; mi++)
        #pragma unroll
        for (int ni = 0; ni < NI; ni++)
            #pragma unroll
            for (int j = 0; j < 4; j++) acc[mi][ni][j] = 0.0f;

    auto prefetch = [&](int it, int st) {
        const int kt = kz0 + it * BK;
        #pragma unroll
        for (int i = 0; i < 4; i++) {
            int ch = tid + i * 256, row = ch >> 3, c = ch & 7;
            cp_async16(sA + st * strA + row * 128 + ((c ^ (row & 7)) << 4),
                       A + (size_t)(m0 + row) * K + kt + c * 8);
        }
        #pragma unroll
        for (int i = 0; i < 4; i++) {
            int ch = tid + i * 256, row = ch >> 3, c = ch & 7;
            cp_async16(sB + st * strB + row * 128 + ((c ^ (row & 7)) << 4),
                       B + (size_t)(n0 + row) * K + kt + c * 8);
        }
        CP_COMMIT();
    };

    auto compute = [&](int st) {
        const uint32_t baseA = sA + st * strA;
        const uint32_t baseB = sB + st * strB;
        const int arow = wm + (lane & 15);
        const int bg = lane >> 3, brin = lane & 7;
        #pragma unroll
        for (int ks = 0; ks < 4; ks++) {
            uint32_t a[MI][4], b[NI][2];
            const int ac = ks * 2 + (lane >> 4);
            #pragma unroll
            for (int mi = 0; mi < MI; mi++) {
                int r = arow + mi * 16;
                ldsm4(a[mi][0], a[mi][1], a[mi][2], a[mi][3],
                      baseA + r * 128 + ((ac ^ (r & 7)) << 4));
            }
            #pragma unroll
            for (int ni = 0; ni < NI; ni += 2) {
                int r = wn + ni * 8 + ((bg & 2) ? 8 : 0) + brin;
                int c = ks * 2 + (bg & 1);
                uint32_t b0, b1, b2, b3;
                ldsm4(b0, b1, b2, b3, baseB + r * 128 + ((c ^ (r & 7)) << 4));
                b[ni][0] = b0; b[ni][1] = b1; b[ni + 1][0] = b2; b[ni + 1][1] = b3;
            }
            #pragma unroll
            for (int mi = 0; mi < MI; mi++)
                #pragma unroll
                for (int ni = 0; ni < NI; ni++)
                    mma16816(acc[mi][ni], a[mi], b[ni]);
        }
    };

    prefetch(0, 0);
    prefetch(1, 1);

    for (int it = 0; it < NT; ++it) {
        if (it == NT - 1) CP_WAIT0();   // tail: last tile fully landed
        else              CP_WAIT1();
        __syncthreads();
        if (it + 2 < NT) prefetch(it + 2, (it + 2) % ST);
        compute(it % ST);
    }

    // ---- epilogue ----
    #pragma unroll
    for (int mi = 0; mi < MI; mi++) {
        const int r0 = m0 + wm + mi * 16 + (lane >> 2);
        const int r1 = r0 + 8;
        #pragma unroll
        for (int ni = 0; ni < NI; ni++) {
            const int col = n0 + wn + ni * 8 + ((lane & 3) * 2);
            if (IS_L1) {
                const float b0v = __ldg(bias + col), b1v = __ldg(bias + col + 1);
                __half2 p0 = __floats2half2_rn(fmaxf(acc[mi][ni][0] + b0v, 0.0f),
                                               fmaxf(acc[mi][ni][1] + b1v, 0.0f));
                __half2 p1 = __floats2half2_rn(fmaxf(acc[mi][ni][2] + b0v, 0.0f),
                                               fmaxf(acc[mi][ni][3] + b1v, 0.0f));
                *(__half2*)(outH + (size_t)r0 * N + col) = p0;
                *(__half2*)(outH + (size_t)r1 * N + col) = p1;
            } else {
                *(float2*)(outF + (size_t)r0 * N + col) = make_float2(acc[mi][ni][0], acc[mi][ni][1]);
                *(float2*)(outF + (size_t)r1 * N + col) = make_float2(acc[mi][ni][2], acc[mi][ni][3]);
            }
        }
    }
}

// ---------------- K1: w1 dequant + x convert (full occupancy, no smem) ----------------
__global__ void __launch_bounds__(256)
prep1_kernel(const int* __restrict__ q1, const float* __restrict__ s1,
             const float* __restrict__ z1, const float* __restrict__ x,
             __half* __restrict__ w1, __half* __restrict__ x16)
{
    if (blockIdx.x < W1B) {
        long long e = ((long long)blockIdx.x * 256 + threadIdx.x) * 16;
        dequant16<11>(q1, s1, z1, w1, e);
    } else {
        const int i = ((blockIdx.x - W1B) * 256 + threadIdx.x) * 16;
        float4 v0 = *(const float4*)(x + i);
        float4 v1 = *(const float4*)(x + i + 4);
        float4 v2 = *(const float4*)(x + i + 8);
        float4 v3 = *(const float4*)(x + i + 12);
        uint4 st0, st1;
        {
            __half2 h0 = __floats2half2_rn(v0.x, v0.y), h1 = __floats2half2_rn(v0.z, v0.w);
            __half2 h2 = __floats2half2_rn(v1.x, v1.y), h3 = __floats2half2_rn(v1.z, v1.w);
            st0.x = *(uint32_t*)&h0; st0.y = *(uint32_t*)&h1;
            st0.z = *(uint32_t*)&h2; st0.w = *(uint32_t*)&h3;
        }
        {
            __half2 h0 = __floats2half2_rn(v2.x, v2.y), h1 = __floats2half2_rn(v2.z, v2.w);
            __half2 h2 = __floats2half2_rn(v3.x, v3.y), h3 = __floats2half2_rn(v3.z, v3.w);
            st1.x = *(uint32_t*)&h0; st1.y = *(uint32_t*)&h1;
            st1.z = *(uint32_t*)&h2; st1.w = *(uint32_t*)&h3;
        }
        uint4* op = (uint4*)(x16 + i);
        op[0] = st0;
        op[1] = st1;
    }
}

// ---------------- K2 fat: gemm1 tiles + w2 dequant backfill ----------------
__global__ void __launch_bounds__(256)
fat_kernel(const __half* __restrict__ x16, const __half* __restrict__ w1,
           const float* __restrict__ b1, __half* __restrict__ h,
           const int* __restrict__ q2, const float* __restrict__ s2,
           const float* __restrict__ z2, __half* __restrict__ w2)
{
    extern __shared__ char smem[];
    if (blockIdx.x < G1B) {
        const int m0 = (blockIdx.x & 3) * 128;
        const int n0 = (blockIdx.x >> 2) * 128;
        gemm_body<true>(smem, m0, n0, 0, D_IN / 64, x16, w1, b1, nullptr, h, D_H, D_IN);
    } else {
        const int j = blockIdx.x - G1B;
        dequant16<13>(q2, s2, z2, w2, (long long)j * 4096 + threadIdx.x * 16);
    }
}

// ---------------- K3: gemm2 split-K=4 -> partials ----------------
__global__ void __launch_bounds__(256)
gemm2_kernel(const __half* __restrict__ h, const __half* __restrict__ w2,
             float* __restrict__ part)
{
    extern __shared__ char smem[];
    const int m0 = blockIdx.y * 128, n0 = blockIdx.x * 128;
    const int kz0 = blockIdx.z * (D_H / SPLITK);
    float* o = part + (size_t)blockIdx.z * B_DIM * D_OUT;
    gemm_body<false>(smem, m0, n0, kz0, (D_H / SPLITK) / 64,
                     h, w2, nullptr, o, nullptr, D_OUT, D_H);
}

// ---------------- K4: split-K reduce + bias (8 outputs/thread, MLP~10) ----------------
__global__ void __launch_bounds__(256)
reduce_kernel(const float* __restrict__ part, const float* __restrict__ bias,
              float* __restrict__ out)
{
    const int i = (blockIdx.x * blockDim.x + threadIdx.x) * 8;
    float4 b0 = *(const float4*)(bias + (i & (D_OUT - 1)));
    float4 b1 = *(const float4*)(bias + ((i + 4) & (D_OUT - 1)));
    float4 r0 = b0, r1 = b1;
    #pragma unroll
    for (int k = 0; k < SPLITK; k++) {
        const float* p = part + (size_t)k * B_DIM * D_OUT + i;
        float4 p0 = *(const float4*)p;
        float4 p1 = *(const float4*)(p + 4);
        r0.x += p0.x; r0.y += p0.y; r0.z += p0.z; r0.w += p0.w;
        r1.x += p1.x; r1.y += p1.y; r1.z += p1.z; r1.w += p1.w;
    }
    *(float4*)(out + i)     = r0;
    *(float4*)(out + i + 4) = r1;
}

extern "C" void kernel_launch(void* const* d_in, const int* in_sizes, int n_in,
                              void* d_out, int out_size)
{
    const float* x  = (const float*)d_in[0];
    const int*   q1 = (const int*)  d_in[1];
    const float* s1 = (const float*)d_in[2];
    const float* z1 = (const float*)d_in[3];
    const float* b1 = (const float*)d_in[4];
    const int*   q2 = (const int*)  d_in[5];
    const float* s2 = (const float*)d_in[6];
    const float* z2 = (const float*)d_in[7];
    const float* b2 = (const float*)d_in[8];
    float* out = (float*)d_out;

    __half *x16, *h, *w1h, *w2h; float* part;
    cudaGetSymbolAddress((void**)&x16, g_x16);
    cudaGetSymbolAddress((void**)&h,   g_h);
    cudaGetSymbolAddress((void**)&w1h, g_w1h);
    cudaGetSymbolAddress((void**)&w2h, g_w2h);
    cudaGetSymbolAddress((void**)&part, g_part);

    constexpr int SMEM = 3 * 128 * 128 * 2;   // 96 KB
    cudaFuncSetAttribute(fat_kernel,   cudaFuncAttributeMaxDynamicSharedMemorySize, SMEM);
    cudaFuncSetAttribute(gemm2_kernel, cudaFuncAttributeMaxDynamicSharedMemorySize, SMEM);

    // K1: w1 dequant + x convert (full occupancy)
    prep1_kernel<<<W1B + XB, 256>>>(q1, s1, z1, x, w1h, x16);

    // K2: gemm1 || w2 dequant backfill
    fat_kernel<<<G1B + W2B, 256, SMEM>>>(x16, w1h, b1, h, q2, s2, z2, w2h);

    // K3: gemm2 split-K=4 partials
    dim3 g2(D_OUT / 128, B_DIM / 128, SPLITK);
    gemm2_kernel<<<g2, 256, SMEM>>>(h, w2h, part);

    // K4: out = sum(partials) + b2
    reduce_kernel<<<(B_DIM * D_OUT) / (256 * 8), 256>>>(part, b2, out);
}

// round 15
// speedup vs baseline: 1.5280x; 1.0025x over previous
#include <cuda_runtime.h>
#include <cuda_fp16.h>
#include <cstdint>

#define B_DIM 512
#define D_IN  2048
#define D_H   8192
#define D_OUT 2048
#define SPLITK 4

#define N1E (D_H * D_IN)               // 16.8M
#define N2E (D_OUT * D_H)              // 16.8M
#define NXE (B_DIM * D_IN)             // 1.05M
#define W1B  (N1E / 4096)              // 4096 w1-dequant blocks
#define XB   (NXE / 4096)              // 256 x-convert blocks
#define G1B  256                       // gemm1 tiles
#define W2B  (N2E / 4096)              // 4096 w2-dequant blocks

// Scratch (static __device__ => allocation-rule safe)
__device__ __half g_x16[B_DIM * D_IN];
__device__ __half g_h[(size_t)B_DIM * D_H];
__device__ __half g_w1h[(size_t)D_H * D_IN];
__device__ __half g_w2h[(size_t)D_OUT * D_H];
__device__ float  g_part[(size_t)SPLITK * B_DIM * D_OUT];

// ---------------- helpers ----------------
__device__ __forceinline__ uint32_t smem_u32(const void* p) {
    uint32_t a;
    asm("{ .reg .u64 t; cvta.to.shared.u64 t, %1; cvt.u32.u64 %0, t; }" : "=r"(a) : "l"(p));
    return a;
}
__device__ __forceinline__ void cp_async16(uint32_t dst, const void* src) {
    asm volatile("cp.async.cg.shared.global [%0], [%1], 16;" :: "r"(dst), "l"(src));
}
#define CP_COMMIT() asm volatile("cp.async.commit_group;" ::: "memory")
#define CP_WAIT1()  asm volatile("cp.async.wait_group 1;" ::: "memory")
#define CP_WAIT0()  asm volatile("cp.async.wait_group 0;" ::: "memory")

__device__ __forceinline__ void ldsm4(uint32_t& r0, uint32_t& r1, uint32_t& r2, uint32_t& r3,
                                      uint32_t addr) {
    asm volatile("ldmatrix.sync.aligned.m8n8.x4.shared.b16 {%0,%1,%2,%3}, [%4];"
                 : "=r"(r0), "=r"(r1), "=r"(r2), "=r"(r3) : "r"(addr));
}
__device__ __forceinline__ void mma16816(float* c, const uint32_t* a, const uint32_t* b) {
    asm volatile("mma.sync.aligned.m16n8k16.row.col.f32.f16.f16.f32 "
                 "{%0,%1,%2,%3}, {%4,%5,%6,%7}, {%8,%9}, {%0,%1,%2,%3};"
                 : "+f"(c[0]), "+f"(c[1]), "+f"(c[2]), "+f"(c[3])
                 : "r"(a[0]), "r"(a[1]), "r"(a[2]), "r"(a[3]), "r"(b[0]), "r"(b[1]));
}

// ---------------- dequant: 16 fp16 elems at offset e (never crosses a group) ----------------
template<int KSHIFT>
__device__ __forceinline__ void dequant16(const int* __restrict__ q, const float* __restrict__ S,
                                          const float* __restrict__ Z, __half* __restrict__ w,
                                          long long e)
{
    const int row = (int)(e >> KSHIFT);
    const int col = (int)(e & ((1 << KSHIFT) - 1));
    const int g   = col >> 7;
    constexpr int NG = 1 << (KSHIFT - 7);

    const int4* qp = (const int4*)(q + e);
    int4 qa = qp[0], qb = qp[1], qc = qp[2], qd = qp[3];
    const float s = __ldg(S + (size_t)row * NG + g);
    const float z = __ldg(Z + (size_t)row * NG + g);

    uint4 st0, st1;
    {
        __half2 h0 = __floats2half2_rn(((float)qa.x - z) * s, ((float)qa.y - z) * s);
        __half2 h1 = __floats2half2_rn(((float)qa.z - z) * s, ((float)qa.w - z) * s);
        __half2 h2 = __floats2half2_rn(((float)qb.x - z) * s, ((float)qb.y - z) * s);
        __half2 h3 = __floats2half2_rn(((float)qb.z - z) * s, ((float)qb.w - z) * s);
        st0.x = *(uint32_t*)&h0; st0.y = *(uint32_t*)&h1;
        st0.z = *(uint32_t*)&h2; st0.w = *(uint32_t*)&h3;
    }
    {
        __half2 h0 = __floats2half2_rn(((float)qc.x - z) * s, ((float)qc.y - z) * s);
        __half2 h1 = __floats2half2_rn(((float)qc.z - z) * s, ((float)qc.w - z) * s);
        __half2 h2 = __floats2half2_rn(((float)qd.x - z) * s, ((float)qd.y - z) * s);
        __half2 h3 = __floats2half2_rn(((float)qd.z - z) * s, ((float)qd.w - z) * s);
        st1.x = *(uint32_t*)&h0; st1.y = *(uint32_t*)&h1;
        st1.z = *(uint32_t*)&h2; st1.w = *(uint32_t*)&h3;
    }
    uint4* wp = (uint4*)(w + e);
    wp[0] = st0;
    wp[1] = st1;
}

// ---------------- GEMM body: 256 thr, 128x128x64 tile, 64x32 warp tile, 3-stage ----------------
template<bool IS_L1>
__device__ __forceinline__ void
gemm_body(char* smem, int m0, int n0, int kz0, int NT,
          const __half* __restrict__ A, const __half* __restrict__ B,
          const float* __restrict__ bias, float* __restrict__ outF,
          __half* __restrict__ outH, int N, int K)
{
    constexpr int BM = 128, BN = 128, ST = 3;
    constexpr int MI = 4, NI = 4;               // 64x32 per warp
    constexpr int BK = 64;

    const int tid = threadIdx.x, wid = tid >> 5, lane = tid & 31;
    const int wm = (wid >> 2) * 64, wn = (wid & 3) * 32;

    const uint32_t sA = smem_u32(smem);
    const uint32_t strA = BM * 128, strB = BN * 128;
    const uint32_t sB = sA + ST * strA;

    float acc[MI][NI][4];
    #pragma unroll
    for (int mi = 0; mi < MI; mi++)
        #pragma unroll
        for (int ni = 0; ni < NI; ni++)
            #pragma unroll
            for (int j = 0; j < 4; j++) acc[mi][ni][j] = 0.0f;

    auto prefetch = [&](int it, int st) {
        const int kt = kz0 + it * BK;
        #pragma unroll
        for (int i = 0; i < 4; i++) {
            int ch = tid + i * 256, row = ch >> 3, c = ch & 7;
            cp_async16(sA + st * strA + row * 128 + ((c ^ (row & 7)) << 4),
                       A + (size_t)(m0 + row) * K + kt + c * 8);
        }
        #pragma unroll
        for (int i = 0; i < 4; i++) {
            int ch = tid + i * 256, row = ch >> 3, c = ch & 7;
            cp_async16(sB + st * strB + row * 128 + ((c ^ (row & 7)) << 4),
                       B + (size_t)(n0 + row) * K + kt + c * 8);
        }
        CP_COMMIT();
    };

    auto compute = [&](int st) {
        const uint32_t baseA = sA + st * strA;
        const uint32_t baseB = sB + st * strB;
        const int arow = wm + (lane & 15);
        const int bg = lane >> 3, brin = lane & 7;
        #pragma unroll
        for (int ks = 0; ks < 4; ks++) {
            uint32_t a[MI][4], b[NI][2];
            const int ac = ks * 2 + (lane >> 4);
            #pragma unroll
            for (int mi = 0; mi < MI; mi++) {
                int r = arow + mi * 16;
                ldsm4(a[mi][0], a[mi][1], a[mi][2], a[mi][3],
                      baseA + r * 128 + ((ac ^ (r & 7)) << 4));
            }
            #pragma unroll
            for (int ni = 0; ni < NI; ni += 2) {
                int r = wn + ni * 8 + ((bg & 2) ? 8 : 0) + brin;
                int c = ks * 2 + (bg & 1);
                uint32_t b0, b1, b2, b3;
                ldsm4(b0, b1, b2, b3, baseB + r * 128 + ((c ^ (r & 7)) << 4));
                b[ni][0] = b0; b[ni][1] = b1; b[ni + 1][0] = b2; b[ni + 1][1] = b3;
            }
            #pragma unroll
            for (int mi = 0; mi < MI; mi++)
                #pragma unroll
                for (int ni = 0; ni < NI; ni++)
                    mma16816(acc[mi][ni], a[mi], b[ni]);
        }
    };

    prefetch(0, 0);
    prefetch(1, 1);

    for (int it = 0; it < NT; ++it) {
        if (it == NT - 1) CP_WAIT0();   // tail: last tile fully landed
        else              CP_WAIT1();
        __syncthreads();
        if (it + 2 < NT) prefetch(it + 2, (it + 2) % ST);
        compute(it % ST);
    }

    // ---- epilogue ----
    #pragma unroll
    for (int mi = 0; mi < MI; mi++) {
        const int r0 = m0 + wm + mi * 16 + (lane >> 2);
        const int r1 = r0 + 8;
        #pragma unroll
        for (int ni = 0; ni < NI; ni++) {
            const int col = n0 + wn + ni * 8 + ((lane & 3) * 2);
            if (IS_L1) {
                const float b0v = __ldg(bias + col), b1v = __ldg(bias + col + 1);
                __half2 p0 = __floats2half2_rn(fmaxf(acc[mi][ni][0] + b0v, 0.0f),
                                               fmaxf(acc[mi][ni][1] + b1v, 0.0f));
                __half2 p1 = __floats2half2_rn(fmaxf(acc[mi][ni][2] + b0v, 0.0f),
                                               fmaxf(acc[mi][ni][3] + b1v, 0.0f));
                *(__half2*)(outH + (size_t)r0 * N + col) = p0;
                *(__half2*)(outH + (size_t)r1 * N + col) = p1;
            } else {
                *(float2*)(outF + (size_t)r0 * N + col) = make_float2(acc[mi][ni][0], acc[mi][ni][1]);
                *(float2*)(outF + (size_t)r1 * N + col) = make_float2(acc[mi][ni][2], acc[mi][ni][3]);
            }
        }
    }
}

// ---------------- K1: w1 dequant + x convert (full occupancy, no smem) ----------------
__global__ void __launch_bounds__(256)
prep1_kernel(const int* __restrict__ q1, const float* __restrict__ s1,
             const float* __restrict__ z1, const float* __restrict__ x,
             __half* __restrict__ w1, __half* __restrict__ x16)
{
    if (blockIdx.x < W1B) {
        long long e = ((long long)blockIdx.x * 256 + threadIdx.x) * 16;
        dequant16<11>(q1, s1, z1, w1, e);
    } else {
        const int i = ((blockIdx.x - W1B) * 256 + threadIdx.x) * 16;
        float4 v0 = *(const float4*)(x + i);
        float4 v1 = *(const float4*)(x + i + 4);
        float4 v2 = *(const float4*)(x + i + 8);
        float4 v3 = *(const float4*)(x + i + 12);
        uint4 st0, st1;
        {
            __half2 h0 = __floats2half2_rn(v0.x, v0.y), h1 = __floats2half2_rn(v0.z, v0.w);
            __half2 h2 = __floats2half2_rn(v1.x, v1.y), h3 = __floats2half2_rn(v1.z, v1.w);
            st0.x = *(uint32_t*)&h0; st0.y = *(uint32_t*)&h1;
            st0.z = *(uint32_t*)&h2; st0.w = *(uint32_t*)&h3;
        }
        {
            __half2 h0 = __floats2half2_rn(v2.x, v2.y), h1 = __floats2half2_rn(v2.z, v2.w);
            __half2 h2 = __floats2half2_rn(v3.x, v3.y), h3 = __floats2half2_rn(v3.z, v3.w);
            st1.x = *(uint32_t*)&h0; st1.y = *(uint32_t*)&h1;
            st1.z = *(uint32_t*)&h2; st1.w = *(uint32_t*)&h3;
        }
        uint4* op = (uint4*)(x16 + i);
        op[0] = st0;
        op[1] = st1;
    }
}

// ---------------- K2 fat: gemm1 tiles + w2 dequant backfill ----------------
__global__ void __launch_bounds__(256)
fat_kernel(const __half* __restrict__ x16, const __half* __restrict__ w1,
           const float* __restrict__ b1, __half* __restrict__ h,
           const int* __restrict__ q2, const float* __restrict__ s2,
           const float* __restrict__ z2, __half* __restrict__ w2)
{
    extern __shared__ char smem[];
    if (blockIdx.x < G1B) {
        const int m0 = (blockIdx.x & 3) * 128;
        const int n0 = (blockIdx.x >> 2) * 128;
        gemm_body<true>(smem, m0, n0, 0, D_IN / 64, x16, w1, b1, nullptr, h, D_H, D_IN);
    } else {
        const int j = blockIdx.x - G1B;
        dequant16<13>(q2, s2, z2, w2, (long long)j * 4096 + threadIdx.x * 16);
    }
}

// ---------------- K3: gemm2 split-K=4 -> partials ----------------
__global__ void __launch_bounds__(256)
gemm2_kernel(const __half* __restrict__ h, const __half* __restrict__ w2,
             float* __restrict__ part)
{
    extern __shared__ char smem[];
    const int m0 = blockIdx.y * 128, n0 = blockIdx.x * 128;
    const int kz0 = blockIdx.z * (D_H / SPLITK);
    float* o = part + (size_t)blockIdx.z * B_DIM * D_OUT;
    gemm_body<false>(smem, m0, n0, kz0, (D_H / SPLITK) / 64,
                     h, w2, nullptr, o, nullptr, D_OUT, D_H);
}

// ---------------- K4: split-K reduce + bias (4 outputs/thread; best measured) ----------------
__global__ void __launch_bounds__(256)
reduce_kernel(const float* __restrict__ part, const float* __restrict__ bias,
              float* __restrict__ out)
{
    int i = (blockIdx.x * blockDim.x + threadIdx.x) * 4;
    float4 bv = *(const float4*)(bias + (i & (D_OUT - 1)));
    float4 r = make_float4(bv.x, bv.y, bv.z, bv.w);
    #pragma unroll
    for (int k = 0; k < SPLITK; k++) {
        float4 p = *(const float4*)(part + (size_t)k * B_DIM * D_OUT + i);
        r.x += p.x; r.y += p.y; r.z += p.z; r.w += p.w;
    }
    *(float4*)(out + i) = r;
}

extern "C" void kernel_launch(void* const* d_in, const int* in_sizes, int n_in,
                              void* d_out, int out_size)
{
    const float* x  = (const float*)d_in[0];
    const int*   q1 = (const int*)  d_in[1];
    const float* s1 = (const float*)d_in[2];
    const float* z1 = (const float*)d_in[3];
    const float* b1 = (const float*)d_in[4];
    const int*   q2 = (const int*)  d_in[5];
    const float* s2 = (const float*)d_in[6];
    const float* z2 = (const float*)d_in[7];
    const float* b2 = (const float*)d_in[8];
    float* out = (float*)d_out;

    __half *x16, *h, *w1h, *w2h; float* part;
    cudaGetSymbolAddress((void**)&x16, g_x16);
    cudaGetSymbolAddress((void**)&h,   g_h);
    cudaGetSymbolAddress((void**)&w1h, g_w1h);
    cudaGetSymbolAddress((void**)&w2h, g_w2h);
    cudaGetSymbolAddress((void**)&part, g_part);

    constexpr int SMEM = 3 * 128 * 128 * 2;   // 96 KB
    cudaFuncSetAttribute(fat_kernel,   cudaFuncAttributeMaxDynamicSharedMemorySize, SMEM);
    cudaFuncSetAttribute(gemm2_kernel, cudaFuncAttributeMaxDynamicSharedMemorySize, SMEM);

    // K1: w1 dequant + x convert (full occupancy)
    prep1_kernel<<<W1B + XB, 256>>>(q1, s1, z1, x, w1h, x16);

    // K2: gemm1 || w2 dequant backfill
    fat_kernel<<<G1B + W2B, 256, SMEM>>>(x16, w1h, b1, h, q2, s2, z2, w2h);

    // K3: gemm2 split-K=4 partials
    dim3 g2(D_OUT / 128, B_DIM / 128, SPLITK);
    gemm2_kernel<<<g2, 256, SMEM>>>(h, w2h, part);

    // K4: out = sum(partials) + b2
    reduce_kernel<<<(B_DIM * D_OUT) / (256 * 4), 256>>>(part, b2, out);
}

// round 16
// speedup vs baseline: 1.5478x; 1.0130x over previous
#include <cuda_runtime.h>
#include <cuda_fp16.h>
#include <cstdint>

#define B_DIM 512
#define D_IN  2048
#define D_H   8192
#define D_OUT 2048
#define SPLITK 4

#define N1E (D_H * D_IN)               // 16.8M
#define N2E (D_OUT * D_H)              // 16.8M
#define NXE (B_DIM * D_IN)             // 1.05M
#define W1B  (N1E / 4096)              // 4096 w1-dequant blocks
#define XB   (NXE / 4096)              // 256 x-convert blocks
#define G1B  256                       // gemm1 tiles
#define W2B  (N2E / 4096)              // 4096 w2-dequant blocks

// Scratch (static __device__ => allocation-rule safe)
__device__ __half g_x16[B_DIM * D_IN];
__device__ __half g_h[(size_t)B_DIM * D_H];
__device__ __half g_w1h[(size_t)D_H * D_IN];
__device__ __half g_w2h[(size_t)D_OUT * D_H];
__device__ float  g_part[(size_t)SPLITK * B_DIM * D_OUT];

// ---------------- helpers ----------------
__device__ __forceinline__ uint32_t smem_u32(const void* p) {
    uint32_t a;
    asm("{ .reg .u64 t; cvta.to.shared.u64 t, %1; cvt.u32.u64 %0, t; }" : "=r"(a) : "l"(p));
    return a;
}
__device__ __forceinline__ void cp_async16(uint32_t dst, const void* src) {
    asm volatile("cp.async.cg.shared.global [%0], [%1], 16;" :: "r"(dst), "l"(src));
}
#define CP_COMMIT() asm volatile("cp.async.commit_group;" ::: "memory")
#define CP_WAIT1()  asm volatile("cp.async.wait_group 1;" ::: "memory")
#define CP_WAIT0()  asm volatile("cp.async.wait_group 0;" ::: "memory")

// PDL intrinsics via PTX (griddepcontrol; sm_90+, valid at plain sm_103)
__device__ __forceinline__ void pdl_wait() {
    asm volatile("griddepcontrol.wait;" ::: "memory");
}
__device__ __forceinline__ void pdl_trigger() {
    asm volatile("griddepcontrol.launch_dependents;" ::: "memory");
}

__device__ __forceinline__ void ldsm4(uint32_t& r0, uint32_t& r1, uint32_t& r2, uint32_t& r3,
                                      uint32_t addr) {
    asm volatile("ldmatrix.sync.aligned.m8n8.x4.shared.b16 {%0,%1,%2,%3}, [%4];"
                 : "=r"(r0), "=r"(r1), "=r"(r2), "=r"(r3) : "r"(addr));
}
__device__ __forceinline__ void mma16816(float* c, const uint32_t* a, const uint32_t* b) {
    asm volatile("mma.sync.aligned.m16n8k16.row.col.f32.f16.f16.f32 "
                 "{%0,%1,%2,%3}, {%4,%5,%6,%7}, {%8,%9}, {%0,%1,%2,%3};"
                 : "+f"(c[0]), "+f"(c[1]), "+f"(c[2]), "+f"(c[3])
                 : "r"(a[0]), "r"(a[1]), "r"(a[2]), "r"(a[3]), "r"(b[0]), "r"(b[1]));
}

// ---------------- dequant: 16 fp16 elems at offset e (never crosses a group) ----------------
template<int KSHIFT>
__device__ __forceinline__ void dequant16(const int* __restrict__ q, const float* __restrict__ S,
                                          const float* __restrict__ Z, __half* __restrict__ w,
                                          long long e)
{
    const int row = (int)(e >> KSHIFT);
    const int col = (int)(e & ((1 << KSHIFT) - 1));
    const int g   = col >> 7;
    constexpr int NG = 1 << (KSHIFT - 7);

    const int4* qp = (const int4*)(q + e);
    int4 qa = qp[0], qb = qp[1], qc = qp[2], qd = qp[3];
    const float s = __ldg(S + (size_t)row * NG + g);
    const float z = __ldg(Z + (size_t)row * NG + g);

    uint4 st0, st1;
    {
        __half2 h0 = __floats2half2_rn(((float)qa.x - z) * s, ((float)qa.y - z) * s);
        __half2 h1 = __floats2half2_rn(((float)qa.z - z) * s, ((float)qa.w - z) * s);
        __half2 h2 = __floats2half2_rn(((float)qb.x - z) * s, ((float)qb.y - z) * s);
        __half2 h3 = __floats2half2_rn(((float)qb.z - z) * s, ((float)qb.w - z) * s);
        st0.x = *(uint32_t*)&h0; st0.y = *(uint32_t*)&h1;
        st0.z = *(uint32_t*)&h2; st0.w = *(uint32_t*)&h3;
    }
    {
        __half2 h0 = __floats2half2_rn(((float)qc.x - z) * s, ((float)qc.y - z) * s);
        __half2 h1 = __floats2half2_rn(((float)qc.z - z) * s, ((float)qc.w - z) * s);
        __half2 h2 = __floats2half2_rn(((float)qd.x - z) * s, ((float)qd.y - z) * s);
        __half2 h3 = __floats2half2_rn(((float)qd.z - z) * s, ((float)qd.w - z) * s);
        st1.x = *(uint32_t*)&h0; st1.y = *(uint32_t*)&h1;
        st1.z = *(uint32_t*)&h2; st1.w = *(uint32_t*)&h3;
    }
    uint4* wp = (uint4*)(w + e);
    wp[0] = st0;
    wp[1] = st1;
}

// ---------------- GEMM body: 256 thr, 128x128x64 tile, 64x32 warp tile, 3-stage ----------------
template<bool IS_L1>
__device__ __forceinline__ void
gemm_body(char* smem, int m0, int n0, int kz0, int NT,
          const __half* __restrict__ A, const __half* __restrict__ B,
          const float* __restrict__ bias, float* __restrict__ outF,
          __half* __restrict__ outH, int N, int K)
{
    constexpr int BM = 128, BN = 128, ST = 3;
    constexpr int MI = 4, NI = 4;               // 64x32 per warp
    constexpr int BK = 64;

    const int tid = threadIdx.x, wid = tid >> 5, lane = tid & 31;
    const int wm = (wid >> 2) * 64, wn = (wid & 3) * 32;

    const uint32_t sA = smem_u32(smem);
    const uint32_t strA = BM * 128, strB = BN * 128;
    const uint32_t sB = sA + ST * strA;

    float acc[MI][NI][4];
    #pragma unroll
    for (int mi = 0; mi < MI; mi++)
        #pragma unroll
        for (int ni = 0; ni < NI; ni++)
            #pragma unroll
            for (int j = 0; j < 4; j++) acc[mi][ni][j] = 0.0f;

    auto prefetch = [&](int it, int st) {
        const int kt = kz0 + it * BK;
        #pragma unroll
        for (int i = 0; i < 4; i++) {
            int ch = tid + i * 256, row = ch >> 3, c = ch & 7;
            cp_async16(sA + st * strA + row * 128 + ((c ^ (row & 7)) << 4),
                       A + (size_t)(m0 + row) * K + kt + c * 8);
        }
        #pragma unroll
        for (int i = 0; i < 4; i++) {
            int ch = tid + i * 256, row = ch >> 3, c = ch & 7;
            cp_async16(sB + st * strB + row * 128 + ((c ^ (row & 7)) << 4),
                       B + (size_t)(n0 + row) * K + kt + c * 8);
        }
        CP_COMMIT();
    };

    auto compute = [&](int st) {
        const uint32_t baseA = sA + st * strA;
        const uint32_t baseB = sB + st * strB;
        const int arow = wm + (lane & 15);
        const int bg = lane >> 3, brin = lane & 7;
        #pragma unroll
        for (int ks = 0; ks < 4; ks++) {
            uint32_t a[MI][4], b[NI][2];
            const int ac = ks * 2 + (lane >> 4);
            #pragma unroll
            for (int mi = 0; mi < MI; mi++) {
                int r = arow + mi * 16;
                ldsm4(a[mi][0], a[mi][1], a[mi][2], a[mi][3],
                      baseA + r * 128 + ((ac ^ (r & 7)) << 4));
            }
            #pragma unroll
            for (int ni = 0; ni < NI; ni += 2) {
                int r = wn + ni * 8 + ((bg & 2) ? 8 : 0) + brin;
                int c = ks * 2 + (bg & 1);
                uint32_t b0, b1, b2, b3;
                ldsm4(b0, b1, b2, b3, baseB + r * 128 + ((c ^ (r & 7)) << 4));
                b[ni][0] = b0; b[ni][1] = b1; b[ni + 1][0] = b2; b[ni + 1][1] = b3;
            }
            #pragma unroll
            for (int mi = 0; mi < MI; mi++)
                #pragma unroll
                for (int ni = 0; ni < NI; ni++)
                    mma16816(acc[mi][ni], a[mi], b[ni]);
        }
    };

    prefetch(0, 0);
    prefetch(1, 1);

    for (int it = 0; it < NT; ++it) {
        if (it == NT - 1) CP_WAIT0();   // tail: last tile fully landed
        else              CP_WAIT1();
        __syncthreads();
        if (it + 2 < NT) prefetch(it + 2, (it + 2) % ST);
        compute(it % ST);
    }

    // ---- epilogue ----
    #pragma unroll
    for (int mi = 0; mi < MI; mi++) {
        const int r0 = m0 + wm + mi * 16 + (lane >> 2);
        const int r1 = r0 + 8;
        #pragma unroll
        for (int ni = 0; ni < NI; ni++) {
            const int col = n0 + wn + ni * 8 + ((lane & 3) * 2);
            if (IS_L1) {
                const float b0v = __ldg(bias + col), b1v = __ldg(bias + col + 1);
                __half2 p0 = __floats2half2_rn(fmaxf(acc[mi][ni][0] + b0v, 0.0f),
                                               fmaxf(acc[mi][ni][1] + b1v, 0.0f));
                __half2 p1 = __floats2half2_rn(fmaxf(acc[mi][ni][2] + b0v, 0.0f),
                                               fmaxf(acc[mi][ni][3] + b1v, 0.0f));
                *(__half2*)(outH + (size_t)r0 * N + col) = p0;
                *(__half2*)(outH + (size_t)r1 * N + col) = p1;
            } else {
                *(float2*)(outF + (size_t)r0 * N + col) = make_float2(acc[mi][ni][0], acc[mi][ni][1]);
                *(float2*)(outF + (size_t)r1 * N + col) = make_float2(acc[mi][ni][2], acc[mi][ni][3]);
            }
        }
    }
}

// ---------------- K1: w1 dequant + x convert (full occupancy, no smem) ----------------
__global__ void __launch_bounds__(256)
prep1_kernel(const int* __restrict__ q1, const float* __restrict__ s1,
             const float* __restrict__ z1, const float* __restrict__ x,
             __half* __restrict__ w1, __half* __restrict__ x16)
{
    if (blockIdx.x < W1B) {
        long long e = ((long long)blockIdx.x * 256 + threadIdx.x) * 16;
        dequant16<11>(q1, s1, z1, w1, e);
    } else {
        const int i = ((blockIdx.x - W1B) * 256 + threadIdx.x) * 16;
        float4 v0 = *(const float4*)(x + i);
        float4 v1 = *(const float4*)(x + i + 4);
        float4 v2 = *(const float4*)(x + i + 8);
        float4 v3 = *(const float4*)(x + i + 12);
        uint4 st0, st1;
        {
            __half2 h0 = __floats2half2_rn(v0.x, v0.y), h1 = __floats2half2_rn(v0.z, v0.w);
            __half2 h2 = __floats2half2_rn(v1.x, v1.y), h3 = __floats2half2_rn(v1.z, v1.w);
            st0.x = *(uint32_t*)&h0; st0.y = *(uint32_t*)&h1;
            st0.z = *(uint32_t*)&h2; st0.w = *(uint32_t*)&h3;
        }
        {
            __half2 h0 = __floats2half2_rn(v2.x, v2.y), h1 = __floats2half2_rn(v2.z, v2.w);
            __half2 h2 = __floats2half2_rn(v3.x, v3.y), h3 = __floats2half2_rn(v3.z, v3.w);
            st1.x = *(uint32_t*)&h0; st1.y = *(uint32_t*)&h1;
            st1.z = *(uint32_t*)&h2; st1.w = *(uint32_t*)&h3;
        }
        uint4* op = (uint4*)(x16 + i);
        op[0] = st0;
        op[1] = st1;
    }
    pdl_trigger();   // allow fat kernel to begin scheduling
}

// ---------------- K2 fat: gemm1 tiles + w2 dequant backfill (PDL-aware) ----------------
__global__ void __launch_bounds__(256)
fat_kernel(const __half* __restrict__ x16, const __half* __restrict__ w1,
           const float* __restrict__ b1, __half* __restrict__ h,
           const int* __restrict__ q2, const float* __restrict__ s2,
           const float* __restrict__ z2, __half* __restrict__ w2)
{
    extern __shared__ char smem[];
    if (blockIdx.x < G1B) {
        pdl_wait();   // gemm1 reads w1h/x16 -> must wait for prep1 completion
        const int m0 = (blockIdx.x & 3) * 128;
        const int n0 = (blockIdx.x >> 2) * 128;
        gemm_body<true>(smem, m0, n0, 0, D_IN / 64, x16, w1, b1, nullptr, h, D_H, D_IN);
    } else {
        // w2 dequant reads only q2/s2/z2 (kernel inputs) -> no dependency, start immediately
        const int j = blockIdx.x - G1B;
        dequant16<13>(q2, s2, z2, w2, (long long)j * 4096 + threadIdx.x * 16);
    }
    pdl_trigger();
}

// ---------------- K3: gemm2 split-K=4 -> partials (PDL-aware) ----------------
__global__ void __launch_bounds__(256)
gemm2_kernel(const __half* __restrict__ h, const __half* __restrict__ w2,
             float* __restrict__ part)
{
    extern __shared__ char smem[];
    pdl_wait();       // needs h + w2 from fat kernel
    const int m0 = blockIdx.y * 128, n0 = blockIdx.x * 128;
    const int kz0 = blockIdx.z * (D_H / SPLITK);
    float* o = part + (size_t)blockIdx.z * B_DIM * D_OUT;
    gemm_body<false>(smem, m0, n0, kz0, (D_H / SPLITK) / 64,
                     h, w2, nullptr, o, nullptr, D_OUT, D_H);
    pdl_trigger();
}

// ---------------- K4: split-K reduce + bias (4 outputs/thread; best measured) ----------------
__global__ void __launch_bounds__(256)
reduce_kernel(const float* __restrict__ part, const float* __restrict__ bias,
              float* __restrict__ out)
{
    pdl_wait();       // needs all partials
    int i = (blockIdx.x * blockDim.x + threadIdx.x) * 4;
    float4 bv = *(const float4*)(bias + (i & (D_OUT - 1)));
    float4 r = make_float4(bv.x, bv.y, bv.z, bv.w);
    #pragma unroll
    for (int k = 0; k < SPLITK; k++) {
        float4 p = *(const float4*)(part + (size_t)k * B_DIM * D_OUT + i);
        r.x += p.x; r.y += p.y; r.z += p.z; r.w += p.w;
    }
    *(float4*)(out + i) = r;
}

extern "C" void kernel_launch(void* const* d_in, const int* in_sizes, int n_in,
                              void* d_out, int out_size)
{
    const float* x  = (const float*)d_in[0];
    const int*   q1 = (const int*)  d_in[1];
    const float* s1 = (const float*)d_in[2];
    const float* z1 = (const float*)d_in[3];
    const float* b1 = (const float*)d_in[4];
    const int*   q2 = (const int*)  d_in[5];
    const float* s2 = (const float*)d_in[6];
    const float* z2 = (const float*)d_in[7];
    const float* b2 = (const float*)d_in[8];
    float* out = (float*)d_out;

    __half *x16, *h, *w1h, *w2h; float* part;
    cudaGetSymbolAddress((void**)&x16, g_x16);
    cudaGetSymbolAddress((void**)&h,   g_h);
    cudaGetSymbolAddress((void**)&w1h, g_w1h);
    cudaGetSymbolAddress((void**)&w2h, g_w2h);
    cudaGetSymbolAddress((void**)&part, g_part);

    constexpr int SMEM = 3 * 128 * 128 * 2;   // 96 KB
    cudaFuncSetAttribute(fat_kernel,   cudaFuncAttributeMaxDynamicSharedMemorySize, SMEM);
    cudaFuncSetAttribute(gemm2_kernel, cudaFuncAttributeMaxDynamicSharedMemorySize, SMEM);

    cudaLaunchAttribute pdl[1];
    pdl[0].id = cudaLaunchAttributeProgrammaticStreamSerialization;
    pdl[0].val.programmaticStreamSerializationAllowed = 1;

    // K1: w1 dequant + x convert (plain launch; triggers PDL for K2)
    prep1_kernel<<<W1B + XB, 256>>>(q1, s1, z1, x, w1h, x16);

    // K2: gemm1 || w2 dequant backfill — PDL: w2 blocks start during prep1's tail
    {
        cudaLaunchConfig_t cfg = {};
        cfg.gridDim = dim3(G1B + W2B, 1, 1);
        cfg.blockDim = dim3(256, 1, 1);
        cfg.dynamicSmemBytes = SMEM;
        cfg.attrs = pdl; cfg.numAttrs = 1;
        cudaLaunchKernelEx(&cfg, fat_kernel, x16, w1h, b1, h, q2, s2, z2, w2h);
    }

    // K3: gemm2 split-K=4 partials — PDL
    {
        cudaLaunchConfig_t cfg = {};
        cfg.gridDim = dim3(D_OUT / 128, B_DIM / 128, SPLITK);
        cfg.blockDim = dim3(256, 1, 1);
        cfg.dynamicSmemBytes = SMEM;
        cfg.attrs = pdl; cfg.numAttrs = 1;
        cudaLaunchKernelEx(&cfg, gemm2_kernel, h, w2h, part);
    }

    // K4: out = sum(partials) + b2 — PDL
    {
        cudaLaunchConfig_t cfg = {};
        cfg.gridDim = dim3((B_DIM * D_OUT) / (256 * 4), 1, 1);
        cfg.blockDim = dim3(256, 1, 1);
        cfg.attrs = pdl; cfg.numAttrs = 1;
        cudaLaunchKernelEx(&cfg, reduce_kernel, part, b2, out);
    }
}